// round 1
// baseline (speedup 1.0000x reference)
#include <cuda_runtime.h>
#include <cstdint>

// ---------------------------------------------------------------------------
// softplus( exp(-0.5*||x_i - c_j||^2) @ beta )
// N=40000 rows of x (D=32), M=4000 centers.
//
// Strategy: each thread owns one x-row, kept packed in registers as 32 b64
// "duplicated" f32x2 values. Centers are staged in shared memory
// pair-interleaved (float2 per k), so the inner loop is:
//      LDS.128 (broadcast) -> fma.rn.f32x2  (2 center-dots per instruction)
// Exponent uses the expansion  -0.5*||x-c||^2 = dot - 0.5*x^2 - 0.5*c^2,
// pre-scaled by log2(e) so the activation is a single MUFU EX2.
// ---------------------------------------------------------------------------

#define LOG2E 1.4426950408889634f

__device__ __forceinline__ unsigned long long pack2(float lo, float hi) {
    unsigned long long r;
    asm("mov.b64 %0, {%1, %2};" : "=l"(r) : "f"(lo), "f"(hi));
    return r;
}

__device__ __forceinline__ void unpack2(unsigned long long v, float& lo, float& hi) {
    asm("mov.b64 {%0, %1}, %2;" : "=f"(lo), "=f"(hi) : "l"(v));
}

__device__ __forceinline__ unsigned long long fma2(unsigned long long a,
                                                   unsigned long long b,
                                                   unsigned long long c) {
    unsigned long long r;
    asm("fma.rn.f32x2 %0, %1, %2, %3;" : "=l"(r) : "l"(a), "l"(b), "l"(c));
    return r;
}

__device__ __forceinline__ float ex2_approx(float x) {
    float r;
    asm("ex2.approx.ftz.f32 %0, %1;" : "=f"(r) : "f"(x));
    return r;
}

constexpr int D     = 32;   // covariate dimension (fixed by problem)
constexpr int TILE  = 80;   // centers per smem chunk (4000 % 80 == 0)
constexpr int PAIRS = TILE / 2;
constexpr int BLOCK = 32;   // 1-warp blocks -> 1250 blocks, ~8.5/SM, low quantization

__global__ void __launch_bounds__(BLOCK)
krr_softplus_kernel(const float* __restrict__ x,
                    const float* __restrict__ c,
                    const float* __restrict__ beta,
                    float* __restrict__ out,
                    int N, int M)
{
    // Pair-interleaved centers: sc[p][k] = (c[2p][k], c[2p+1][k])
    __shared__ __align__(16) float2 sc[PAIRS][D];
    __shared__ float sa[TILE];   // -0.5 * ||c_j||^2 * log2(e)
    __shared__ float sb[TILE];   // beta_j

    const int row = blockIdx.x * BLOCK + threadIdx.x;
    const int safe_row = (row < N) ? row : 0;

    // Load x row, compute ||x||^2, pre-pack duplicated f32x2 operands.
    unsigned long long xd[D];
    float xsq = 0.f;
    {
        const float4* xp = reinterpret_cast<const float4*>(x + (size_t)safe_row * D);
        #pragma unroll
        for (int q = 0; q < D / 4; q++) {
            float4 v = xp[q];
            xsq += v.x * v.x + v.y * v.y + v.z * v.z + v.w * v.w;
            xd[4 * q + 0] = pack2(v.x, v.x);
            xd[4 * q + 1] = pack2(v.y, v.y);
            xd[4 * q + 2] = pack2(v.z, v.z);
            xd[4 * q + 3] = pack2(v.w, v.w);
        }
    }
    const float bx = -0.5f * xsq * LOG2E;

    float acc = 0.f;

    for (int j0 = 0; j0 < M; j0 += TILE) {
        __syncthreads();  // previous chunk fully consumed

        // Cooperative load of TILE centers into pair-interleaved smem.
        for (int idx = threadIdx.x; idx < TILE * D; idx += BLOCK) {
            int jj = idx >> 5;        // local center index
            int k  = idx & 31;        // covariate index (coalesced across lanes)
            int j  = j0 + jj;
            float v = (j < M) ? c[(size_t)j * D + k] : 0.f;
            reinterpret_cast<float*>(&sc[jj >> 1][k])[jj & 1] = v;
        }
        __syncthreads();

        // Per-center terms: -0.5*||c||^2*log2e and beta.
        for (int jj = threadIdx.x; jj < TILE; jj += BLOCK) {
            int j = j0 + jj;
            float cs = 0.f;
            #pragma unroll
            for (int k = 0; k < D; k++) {
                float v = reinterpret_cast<float*>(&sc[jj >> 1][k])[jj & 1];
                cs = fmaf(v, v, cs);
            }
            sa[jj] = -0.5f * cs * LOG2E;
            sb[jj] = (j < M) ? beta[j] : 0.f;
        }
        __syncthreads();

        // Main loop: 2 centers per pass via packed f32x2 FMA.
        #pragma unroll 2
        for (int p = 0; p < PAIRS; p++) {
            const ulonglong2* cp = reinterpret_cast<const ulonglong2*>(sc[p]);
            unsigned long long d2a = 0ull;   // bit pattern == (0.f, 0.f)
            unsigned long long d2b = 0ull;
            #pragma unroll
            for (int q = 0; q < D / 2; q++) {
                ulonglong2 w = cp[q];                 // LDS.128 broadcast
                d2a = fma2(xd[2 * q + 0], w.x, d2a);  // even-k partials
                d2b = fma2(xd[2 * q + 1], w.y, d2b);  // odd-k partials
            }
            float da0, da1, db0, db1;
            unpack2(d2a, da0, da1);
            unpack2(d2b, db0, db1);
            float dot0 = da0 + db0;
            float dot1 = da1 + db1;

            float a0 = sa[2 * p + 0] + bx;
            float a1 = sa[2 * p + 1] + bx;
            float e0 = ex2_approx(fmaf(dot0, LOG2E, a0));
            float e1 = ex2_approx(fmaf(dot1, LOG2E, a1));
            acc = fmaf(sb[2 * p + 0], e0, acc);
            acc = fmaf(sb[2 * p + 1], e1, acc);
        }
    }

    if (row < N) {
        // numerically stable softplus
        float sp = fmaxf(acc, 0.f) + log1pf(expf(-fabsf(acc)));
        out[row] = sp;
    }
}

extern "C" void kernel_launch(void* const* d_in, const int* in_sizes, int n_in,
                              void* d_out, int out_size) {
    const float* x    = (const float*)d_in[0];  // (N, 32)
    const float* c    = (const float*)d_in[1];  // (M, 32)
    const float* beta = (const float*)d_in[2];  // (M,)
    float* out = (float*)d_out;                 // (N,)

    const int M = in_sizes[2];
    const int N = out_size;

    const int grid = (N + BLOCK - 1) / BLOCK;
    krr_softplus_kernel<<<grid, BLOCK>>>(x, c, beta, out, N, M);
}

// round 2
// speedup vs baseline: 2.2354x; 2.2354x over previous
#include <cuda_runtime.h>
#include <cstdint>

// ---------------------------------------------------------------------------
// softplus( exp(-0.5*||x_i - c_j||^2) @ beta ),  N=40000, M=4000, D=32.
//
// R2 design:
//  * 128-thread blocks, 32 rows/block (1 row per lane).
//  * 4-way M-split across warps: warp w handles centers [w*M/4,(w+1)*M/4),
//    partials combined through shared memory at the end.
//  * x row kept as 16 b64 regs (adjacent-dim pairs, natural memory layout);
//    inner loop = LDS.128 (broadcast) + fma.rn.f32x2, 4 centers in flight
//    (4 independent accumulation chains).
//  * Per-warp double-buffered center tiles loaded with cp.async (LDGSTS).
//  * Per-center constants g = -0.5*||c||^2*log2e and beta precomputed by a
//    prep kernel into a __device__ global (padded so OOB centers contribute 0).
// ---------------------------------------------------------------------------

#define LOG2E 1.4426950408889634f

constexpr int D      = 32;
constexpr int BLOCK  = 128;
constexpr int WARPS  = 4;
constexpr int ROWS   = 32;    // rows per block (one per lane)
constexpr int TILE   = 40;    // centers per tile per warp
constexpr int MAXM   = 4352;  // padded capacity for per-center constants

__device__ float2 g_gb[MAXM];   // (.x = -0.5*||c||^2*log2e, .y = beta)

__device__ __forceinline__ unsigned long long fma2(unsigned long long a,
                                                   unsigned long long b,
                                                   unsigned long long c) {
    unsigned long long r;
    asm("fma.rn.f32x2 %0, %1, %2, %3;" : "=l"(r) : "l"(a), "l"(b), "l"(c));
    return r;
}

__device__ __forceinline__ void unpack2(unsigned long long v, float& lo, float& hi) {
    asm("mov.b64 {%0, %1}, %2;" : "=f"(lo), "=f"(hi) : "l"(v));
}

__device__ __forceinline__ float ex2_approx(float x) {
    float r;
    asm("ex2.approx.ftz.f32 %0, %1;" : "=f"(r) : "f"(x));
    return r;
}

__device__ __forceinline__ void cp_async16(void* smem_dst, const void* gsrc) {
    uint32_t s = (uint32_t)__cvta_generic_to_shared(smem_dst);
    asm volatile("cp.async.ca.shared.global [%0], [%1], 16;\n" :: "r"(s), "l"(gsrc));
}
#define CP_COMMIT() asm volatile("cp.async.commit_group;\n" ::: "memory")
#define CP_WAIT1()  asm volatile("cp.async.wait_group 1;\n" ::: "memory")

// ---------------------------------------------------------------------------
// Prep: per-center constants (g, beta), padded region gets (-inf-ish, 0) so
// any out-of-range center contributes exactly 0 (ex2(-1e30) flushes to 0).
// ---------------------------------------------------------------------------
__global__ void prep_kernel(const float* __restrict__ c,
                            const float* __restrict__ beta, int M) {
    int j = blockIdx.x * blockDim.x + threadIdx.x;
    if (j >= MAXM) return;
    if (j < M) {
        const float4* cp = reinterpret_cast<const float4*>(c + (size_t)j * D);
        float s = 0.f;
        #pragma unroll
        for (int q = 0; q < D / 4; q++) {
            float4 v = cp[q];
            s = fmaf(v.x, v.x, fmaf(v.y, v.y, fmaf(v.z, v.z, fmaf(v.w, v.w, s))));
        }
        g_gb[j] = make_float2(-0.5f * s * LOG2E, beta[j]);
    } else {
        g_gb[j] = make_float2(-1e30f, 0.f);
    }
}

// ---------------------------------------------------------------------------
// Main kernel.
// ---------------------------------------------------------------------------
__global__ void __launch_bounds__(BLOCK)
krr_softplus_kernel(const float* __restrict__ x,
                    const float* __restrict__ c,
                    float* __restrict__ out,
                    int N, int M)
{
    // Per-warp double-buffered tiles: TILE centers x D floats = 5 KB/buffer.
    __shared__ __align__(16) float4 sbuf[WARPS][2][TILE * D / 4];  // 40 KB
    __shared__ __align__(16) float2 sgb [WARPS][2][TILE];          // 2.5 KB
    __shared__ float spart[WARPS][ROWS + 1];

    const int w    = threadIdx.x >> 5;
    const int lane = threadIdx.x & 31;
    const int row  = blockIdx.x * ROWS + lane;
    const int safe_row = (row < N) ? row : 0;

    // Per-warp center range (M assumed divisible by WARPS; remainder -> warp 3).
    const int mper  = (M + WARPS - 1) / WARPS;
    const int jbeg  = w * mper;
    const int jend  = min(M, jbeg + mper);
    const int ntile = (jend - jbeg + TILE - 1) / TILE;   // tiles for this warp

    // x row: 16 b64 values (adjacent-dim pairs, natural layout) + ||x||^2.
    unsigned long long xd[D / 2];
    float xsq = 0.f;
    {
        const ulonglong2* xp = reinterpret_cast<const ulonglong2*>(x + (size_t)safe_row * D);
        #pragma unroll
        for (int q = 0; q < D / 4; q++) {
            ulonglong2 v = xp[q];
            xd[2 * q + 0] = v.x;
            xd[2 * q + 1] = v.y;
            float a, b;
            unpack2(v.x, a, b); xsq = fmaf(a, a, fmaf(b, b, xsq));
            unpack2(v.y, a, b); xsq = fmaf(a, a, fmaf(b, b, xsq));
        }
    }
    const float bx = -0.5f * xsq * LOG2E;

    // --- tile fetch helper (cp.async, per warp) ---
    // tile t covers centers [jbeg + t*TILE, ...). Clamp the source so OOB
    // lanes fetch valid memory; their contribution is killed via g_gb padding.
    auto issue_tile = [&](int t, int buf) {
        long j0 = (long)jbeg + (long)t * TILE;
        // center data: TILE*D floats = 320 float4, 32 lanes x 10 chunks
        const float4* src = reinterpret_cast<const float4*>(c) + j0 * (D / 4);
        const float4* src_last = reinterpret_cast<const float4*>(c) + ((long)M * D / 4 - 1);
        float4* dst = sbuf[w][buf];
        #pragma unroll
        for (int i = 0; i < TILE * D / 4 / 32; i++) {
            const float4* s = src + lane + 32 * i;
            if (s > src_last) s = src_last;
            cp_async16(dst + lane + 32 * i, s);
        }
        // per-center constants: TILE float2 = 320 B = 20 x 16 B
        if (lane < TILE / 2) {
            long jj = j0 + lane * 2;
            if (jj > MAXM - 2) jj = MAXM - 2;
            cp_async16(&sgb[w][buf][lane * 2], &g_gb[jj]);
        }
    };

    float acc = 0.f;

    issue_tile(0, 0);
    CP_COMMIT();

    for (int t = 0; t < ntile; t++) {
        const int buf = t & 1;
        if (t + 1 < ntile) issue_tile(t + 1, buf ^ 1);
        CP_COMMIT();          // committed even if empty: keeps group count uniform
        CP_WAIT1();           // tile t resident
        __syncwarp();

        const float*  tb = reinterpret_cast<const float*>(sbuf[w][buf]);
        const float2* gb = sgb[w][buf];

        const int ncent = min(TILE, jend - (jbeg + t * TILE));
        // full tiles are the common case (TILE | mper); tail handled by clamp+pad
        #pragma unroll 1
        for (int g = 0; g < TILE; g += 4) {
            const ulonglong2* c0 = reinterpret_cast<const ulonglong2*>(tb + (g + 0) * D);
            const ulonglong2* c1 = reinterpret_cast<const ulonglong2*>(tb + (g + 1) * D);
            const ulonglong2* c2 = reinterpret_cast<const ulonglong2*>(tb + (g + 2) * D);
            const ulonglong2* c3 = reinterpret_cast<const ulonglong2*>(tb + (g + 3) * D);

            unsigned long long a0 = 0ull, a1 = 0ull, a2 = 0ull, a3 = 0ull;
            #pragma unroll
            for (int q = 0; q < D / 4; q++) {
                ulonglong2 w0 = c0[q];
                ulonglong2 w1 = c1[q];
                ulonglong2 w2 = c2[q];
                ulonglong2 w3 = c3[q];
                a0 = fma2(xd[2 * q + 0], w0.x, a0);
                a1 = fma2(xd[2 * q + 0], w1.x, a1);
                a2 = fma2(xd[2 * q + 0], w2.x, a2);
                a3 = fma2(xd[2 * q + 0], w3.x, a3);
                a0 = fma2(xd[2 * q + 1], w0.y, a0);
                a1 = fma2(xd[2 * q + 1], w1.y, a1);
                a2 = fma2(xd[2 * q + 1], w2.y, a2);
                a3 = fma2(xd[2 * q + 1], w3.y, a3);
            }

            float lo, hi, dot, e;
            float2 q0 = gb[g + 0], q1 = gb[g + 1], q2 = gb[g + 2], q3 = gb[g + 3];

            unpack2(a0, lo, hi); dot = lo + hi;
            e = ex2_approx(fmaf(dot, LOG2E, q0.x + bx));
            acc = fmaf(q0.y, e, acc);

            unpack2(a1, lo, hi); dot = lo + hi;
            e = ex2_approx(fmaf(dot, LOG2E, q1.x + bx));
            acc = fmaf(q1.y, e, acc);

            unpack2(a2, lo, hi); dot = lo + hi;
            e = ex2_approx(fmaf(dot, LOG2E, q2.x + bx));
            acc = fmaf(q2.y, e, acc);

            unpack2(a3, lo, hi); dot = lo + hi;
            e = ex2_approx(fmaf(dot, LOG2E, q3.x + bx));
            acc = fmaf(q3.y, e, acc);
        }
        (void)ncent;
        __syncwarp();   // all lanes done with buf before it is refilled
    }

    // combine the 4 per-warp partials
    spart[w][lane] = acc;
    __syncthreads();

    if (w == 0 && row < N) {
        float s = spart[0][lane] + spart[1][lane] + spart[2][lane] + spart[3][lane];
        out[row] = fmaxf(s, 0.f) + log1pf(expf(-fabsf(s)));
    }
}

extern "C" void kernel_launch(void* const* d_in, const int* in_sizes, int n_in,
                              void* d_out, int out_size) {
    const float* x    = (const float*)d_in[0];  // (N, 32)
    const float* c    = (const float*)d_in[1];  // (M, 32)
    const float* beta = (const float*)d_in[2];  // (M,)
    float* out = (float*)d_out;                 // (N,)

    const int M = in_sizes[2];
    const int N = out_size;

    prep_kernel<<<(MAXM + 127) / 128, 128>>>(c, beta, M);

    const int grid = (N + ROWS - 1) / ROWS;
    krr_softplus_kernel<<<grid, BLOCK>>>(x, c, out, N, M);
}

// round 3
// speedup vs baseline: 3.1583x; 1.4129x over previous
#include <cuda_runtime.h>
#include <cstdint>

// ---------------------------------------------------------------------------
// softplus( exp(-0.5*||x_i - c_j||^2) @ beta ),  N=40000, M=4000, D=32.
//
// R3 design:
//  * 128-thread blocks, 96 rows/block (3 rows per lane) -> 3x smem reuse.
//  * 4-way M-split across warps, partials combined via shared memory.
//  * Inner loop: LDS.128 broadcast + fma.rn.f32x2, 6 independent chains
//    (3 rows x 2 centers).
//  * Center tiles + per-center constants fetched with cp.async.bulk (TMA
//    bulk copy) into per-warp double buffers; mbarrier completion. This
//    removes ~20M scalar LDGSTS ops from the LSU/L1TEX path.
//  * Per-center constants g = -0.5*||c||^2*log2e and beta precomputed by a
//    prep kernel into a padded __device__ global (padding has beta=0, so
//    out-of-range tile entries contribute exactly 0).
// ---------------------------------------------------------------------------

#define LOG2E 1.4426950408889634f

constexpr int D      = 32;
constexpr int BLOCK  = 128;
constexpr int WARPS  = 4;
constexpr int RPL    = 3;            // rows per lane
constexpr int ROWSB  = 32 * RPL;     // rows per block = 96
constexpr int TILE   = 40;           // centers per tile per warp
constexpr int MAXM   = 4352;         // padded capacity for per-center constants

constexpr int TILE_DATA_BYTES = TILE * D * 4;          // 5120
constexpr int TILE_GB_BYTES   = TILE * 8;              // 320
constexpr unsigned TILE_TX    = TILE_DATA_BYTES + TILE_GB_BYTES;

__device__ float2 g_gb[MAXM];   // (.x = -0.5*||c||^2*log2e, .y = beta)

typedef unsigned long long ull;

__device__ __forceinline__ ull fma2(ull a, ull b, ull c) {
    ull r;
    asm("fma.rn.f32x2 %0, %1, %2, %3;" : "=l"(r) : "l"(a), "l"(b), "l"(c));
    return r;
}

__device__ __forceinline__ void unpack2(ull v, float& lo, float& hi) {
    asm("mov.b64 {%0, %1}, %2;" : "=f"(lo), "=f"(hi) : "l"(v));
}

__device__ __forceinline__ float ex2_approx(float x) {
    float r;
    asm("ex2.approx.ftz.f32 %0, %1;" : "=f"(r) : "f"(x));
    return r;
}

__device__ __forceinline__ void mbar_init(uint32_t mb, int count) {
    asm volatile("mbarrier.init.shared.b64 [%0], %1;" :: "r"(mb), "r"(count) : "memory");
}

__device__ __forceinline__ void mbar_expect_tx(uint32_t mb, uint32_t bytes) {
    asm volatile("mbarrier.arrive.expect_tx.shared.b64 _, [%0], %1;"
                 :: "r"(mb), "r"(bytes) : "memory");
}

__device__ __forceinline__ void bulk_g2s(uint32_t sdst, const void* gsrc,
                                         uint32_t bytes, uint32_t mb) {
    asm volatile(
        "cp.async.bulk.shared::cta.global.mbarrier::complete_tx::bytes "
        "[%0], [%1], %2, [%3];"
        :: "r"(sdst), "l"(gsrc), "r"(bytes), "r"(mb) : "memory");
}

__device__ __forceinline__ void mbar_wait(uint32_t mb, uint32_t parity) {
    uint32_t done;
    asm volatile(
        "{\n\t"
        ".reg .pred p;\n\t"
        "mbarrier.try_wait.parity.acquire.cta.shared::cta.b64 p, [%1], %2;\n\t"
        "selp.b32 %0, 1, 0, p;\n\t"
        "}"
        : "=r"(done) : "r"(mb), "r"(parity) : "memory");
    if (!done) {
        asm volatile(
            "{\n\t"
            ".reg .pred P1;\n\t"
            "WAIT_LOOP_%=:\n\t"
            "mbarrier.try_wait.parity.acquire.cta.shared::cta.b64 P1, [%0], %1, 0x989680;\n\t"
            "@P1 bra.uni WAIT_DONE_%=;\n\t"
            "bra.uni WAIT_LOOP_%=;\n\t"
            "WAIT_DONE_%=:\n\t"
            "}"
            :: "r"(mb), "r"(parity) : "memory");
    }
}

// ---------------------------------------------------------------------------
// Prep: per-center constants (g, beta); padding gets (-1e30, 0) so any
// out-of-range tile entry contributes exactly 0 (ex2 flushes to 0, beta=0).
// ---------------------------------------------------------------------------
__global__ void prep_kernel(const float* __restrict__ c,
                            const float* __restrict__ beta, int M) {
    int j = blockIdx.x * blockDim.x + threadIdx.x;
    if (j >= MAXM) return;
    if (j < M) {
        const float4* cp = reinterpret_cast<const float4*>(c + (size_t)j * D);
        float s = 0.f;
        #pragma unroll
        for (int q = 0; q < D / 4; q++) {
            float4 v = cp[q];
            s = fmaf(v.x, v.x, fmaf(v.y, v.y, fmaf(v.z, v.z, fmaf(v.w, v.w, s))));
        }
        g_gb[j] = make_float2(-0.5f * s * LOG2E, beta[j]);
    } else {
        g_gb[j] = make_float2(-1e30f, 0.f);
    }
}

// ---------------------------------------------------------------------------
// Main kernel.
// ---------------------------------------------------------------------------
__global__ void __launch_bounds__(BLOCK, 3)
krr_softplus_kernel(const float* __restrict__ x,
                    const float* __restrict__ c,
                    float* __restrict__ out,
                    int N, int M)
{
    __shared__ __align__(128) float  sdata[WARPS][2][TILE * D];   // 40 KB
    __shared__ __align__(16)  float2 sgb  [WARPS][2][TILE];       // 2.5 KB
    __shared__ __align__(8)   ull    smbar[WARPS][2];
    __shared__ float spart[WARPS][ROWSB];

    const int tid  = threadIdx.x;
    const int w    = tid >> 5;
    const int lane = tid & 31;

    // mbarrier init (count=1: single expect_tx arrive per tile)
    if (tid == 0) {
        for (int i = 0; i < WARPS; i++) {
            mbar_init((uint32_t)__cvta_generic_to_shared(&smbar[i][0]), 1);
            mbar_init((uint32_t)__cvta_generic_to_shared(&smbar[i][1]), 1);
        }
    }
    asm volatile("fence.proxy.async.shared::cta;" ::: "memory");
    __syncthreads();

    // Per-warp center range.
    const int mper  = (M + WARPS - 1) / WARPS;
    const int jbeg  = w * mper;
    const int jend  = min(M, jbeg + mper);
    const int ntile = (jend > jbeg) ? (jend - jbeg + TILE - 1) / TILE : 0;

    // Load 3 x-rows into b64 regs (adjacent-dim pairs) + per-row bias.
    const int r0 = blockIdx.x * ROWSB + lane;
    const int r1 = r0 + 32;
    const int r2 = r0 + 64;
    ull x0[D / 2], x1[D / 2], x2[D / 2];
    float bx0, bx1, bx2;
    {
        const ull* p0 = reinterpret_cast<const ull*>(x + (size_t)min(r0, N - 1) * D);
        const ull* p1 = reinterpret_cast<const ull*>(x + (size_t)min(r1, N - 1) * D);
        const ull* p2 = reinterpret_cast<const ull*>(x + (size_t)min(r2, N - 1) * D);
        float s0 = 0.f, s1 = 0.f, s2 = 0.f;
        #pragma unroll
        for (int q = 0; q < D / 2; q++) {
            x0[q] = p0[q]; x1[q] = p1[q]; x2[q] = p2[q];
            float a, b;
            unpack2(x0[q], a, b); s0 = fmaf(a, a, fmaf(b, b, s0));
            unpack2(x1[q], a, b); s1 = fmaf(a, a, fmaf(b, b, s1));
            unpack2(x2[q], a, b); s2 = fmaf(a, a, fmaf(b, b, s2));
        }
        bx0 = -0.5f * s0 * LOG2E;
        bx1 = -0.5f * s1 * LOG2E;
        bx2 = -0.5f * s2 * LOG2E;
    }

    // Bulk-copy one tile (data + constants) into buffer `buf`.
    auto issue_tile = [&](int t, int buf) {
        if (lane == 0) {
            long j0 = (long)jbeg + (long)t * TILE;
            long j0d = j0;                       // clamp data src to valid memory;
            if (j0d > (long)M - TILE) j0d = (long)M - TILE;  // gb padding zeroes tail
            uint32_t mb = (uint32_t)__cvta_generic_to_shared(&smbar[w][buf]);
            mbar_expect_tx(mb, TILE_TX);
            bulk_g2s((uint32_t)__cvta_generic_to_shared(&sdata[w][buf][0]),
                     c + j0d * D, TILE_DATA_BYTES, mb);
            bulk_g2s((uint32_t)__cvta_generic_to_shared(&sgb[w][buf][0]),
                     &g_gb[j0], TILE_GB_BYTES, mb);
        }
    };

    float acc0 = 0.f, acc1 = 0.f, acc2 = 0.f;

    if (ntile > 0) issue_tile(0, 0);

    for (int t = 0; t < ntile; t++) {
        const int buf = t & 1;
        if (t + 1 < ntile) issue_tile(t + 1, buf ^ 1);

        uint32_t mb = (uint32_t)__cvta_generic_to_shared(&smbar[w][buf]);
        mbar_wait(mb, (t >> 1) & 1);

        const float*  tb = sdata[w][buf];
        const float2* gb = sgb[w][buf];

        #pragma unroll 1
        for (int g = 0; g < TILE; g += 2) {
            const ulonglong2* c0 = reinterpret_cast<const ulonglong2*>(tb + (g + 0) * D);
            const ulonglong2* c1 = reinterpret_cast<const ulonglong2*>(tb + (g + 1) * D);

            ull a00 = 0ull, a10 = 0ull, a20 = 0ull;   // center g
            ull a01 = 0ull, a11 = 0ull, a21 = 0ull;   // center g+1
            #pragma unroll
            for (int q = 0; q < D / 4; q++) {
                ulonglong2 w0 = c0[q];                // LDS.128 broadcast
                ulonglong2 w1 = c1[q];
                a00 = fma2(x0[2 * q], w0.x, a00);
                a10 = fma2(x1[2 * q], w0.x, a10);
                a20 = fma2(x2[2 * q], w0.x, a20);
                a01 = fma2(x0[2 * q], w1.x, a01);
                a11 = fma2(x1[2 * q], w1.x, a11);
                a21 = fma2(x2[2 * q], w1.x, a21);
                a00 = fma2(x0[2 * q + 1], w0.y, a00);
                a10 = fma2(x1[2 * q + 1], w0.y, a10);
                a20 = fma2(x2[2 * q + 1], w0.y, a20);
                a01 = fma2(x0[2 * q + 1], w1.y, a01);
                a11 = fma2(x1[2 * q + 1], w1.y, a11);
                a21 = fma2(x2[2 * q + 1], w1.y, a21);
            }

            float2 q0 = gb[g], q1 = gb[g + 1];
            float lo, hi, e;

            unpack2(a00, lo, hi);
            e = ex2_approx(fmaf(lo + hi, LOG2E, q0.x + bx0));
            acc0 = fmaf(q0.y, e, acc0);
            unpack2(a10, lo, hi);
            e = ex2_approx(fmaf(lo + hi, LOG2E, q0.x + bx1));
            acc1 = fmaf(q0.y, e, acc1);
            unpack2(a20, lo, hi);
            e = ex2_approx(fmaf(lo + hi, LOG2E, q0.x + bx2));
            acc2 = fmaf(q0.y, e, acc2);

            unpack2(a01, lo, hi);
            e = ex2_approx(fmaf(lo + hi, LOG2E, q1.x + bx0));
            acc0 = fmaf(q1.y, e, acc0);
            unpack2(a11, lo, hi);
            e = ex2_approx(fmaf(lo + hi, LOG2E, q1.x + bx1));
            acc1 = fmaf(q1.y, e, acc1);
            unpack2(a21, lo, hi);
            e = ex2_approx(fmaf(lo + hi, LOG2E, q1.x + bx2));
            acc2 = fmaf(q1.y, e, acc2);
        }
        __syncwarp();   // all lanes done with buf before it is refilled
    }

    // Combine per-warp partials and finish.
    spart[w][lane +  0] = acc0;
    spart[w][lane + 32] = acc1;
    spart[w][lane + 64] = acc2;
    __syncthreads();

    if (tid < ROWSB) {
        int r = blockIdx.x * ROWSB + tid;
        if (r < N) {
            float s = spart[0][tid] + spart[1][tid] + spart[2][tid] + spart[3][tid];
            out[r] = fmaxf(s, 0.f) + log1pf(expf(-fabsf(s)));
        }
    }
}

extern "C" void kernel_launch(void* const* d_in, const int* in_sizes, int n_in,
                              void* d_out, int out_size) {
    const float* x    = (const float*)d_in[0];  // (N, 32)
    const float* c    = (const float*)d_in[1];  // (M, 32)
    const float* beta = (const float*)d_in[2];  // (M,)
    float* out = (float*)d_out;                 // (N,)

    const int M = in_sizes[2];
    const int N = out_size;

    prep_kernel<<<(MAXM + 127) / 128, 128>>>(c, beta, M);

    const int grid = (N + ROWSB - 1) / ROWSB;
    krr_softplus_kernel<<<grid, BLOCK>>>(x, c, out, N, M);
}

// round 5
// speedup vs baseline: 8.6431x; 2.7366x over previous
#include <cuda_runtime.h>
#include <cuda_bf16.h>
#include <cstdint>

// ---------------------------------------------------------------------------
// softplus( exp(-0.5*||x_i - c_j||^2) @ beta ),  N=40000, M=4000, D=32.
//
// R5: bf16-split K=64 GEMM on mma.sync (m16n8k16, base-ISA HMMA path; tcgen05
// is not available because the harness targets compute_103 without 'a') with
// a fully-fused exponent epilogue:
//   d    = x . (c * log2e)          (exact bf16 hi/lo split, fp32 accum)
//   e    = ex2(d + G_j),  G_j = -0.5*||c||^2*log2e + log2(beta_j)
//   row  = ex2(bx_i) * sum_j e,  bx_i = -0.5*||x||^2*log2e
// Prep kernels build SW128-swizzled bf16 [hi|lo] images (128B/row, K=64) so
// ldmatrix is bank-conflict-free; center tiles stream through double-buffered
// smem via cp.async.bulk + mbarrier.
// Each warp owns 16 rows (one m16); per-row sums reduced with 2 shfl.bfly.
// ---------------------------------------------------------------------------

#define LOG2E 1.4426950408889634f
typedef unsigned long long ull;

constexpr int D     = 32;
constexpr int RC    = 64;        // rows per CTA
constexpr int NB    = 128;       // centers per tile
constexpr int MAXR  = 40960;     // row capacity (multiple of 64)
constexpr int MAXM  = 8192;      // center capacity (multiple of 128)
constexpr int ROWB  = 128;       // bytes per image row (64 bf16)

__device__ __align__(128) uint8_t g_xI[(size_t)MAXR * ROWB];  // x  [hi|lo]
__device__ __align__(128) uint8_t g_cI[(size_t)MAXM * ROWB];  // c  [hi|lo] (scaled by log2e)
__device__ float g_G[MAXM];      // -0.5*||c||^2*log2e + log2(beta)
__device__ float g_bx[MAXR];     // -0.5*||x||^2*log2e

__host__ __device__ __forceinline__ uint32_t sw128(uint32_t off) {
    return off ^ ((off >> 3) & 0x70);
}

__device__ __forceinline__ float ex2_approx(float x) {
    float r;
    asm("ex2.approx.ftz.f32 %0, %1;" : "=f"(r) : "f"(x));
    return r;
}

__device__ __forceinline__ uint32_t pack_bf2(float a, float b) {
    __nv_bfloat16 ha = __float2bfloat16(a), hb = __float2bfloat16(b);
    unsigned short ua = *reinterpret_cast<unsigned short*>(&ha);
    unsigned short ub = *reinterpret_cast<unsigned short*>(&hb);
    return (uint32_t)ua | ((uint32_t)ub << 16);
}

// ---- async copy / mbarrier -------------------------------------------------
__device__ __forceinline__ void mbar_init(uint32_t mb, int count) {
    asm volatile("mbarrier.init.shared.b64 [%0], %1;" :: "r"(mb), "r"(count) : "memory");
}
__device__ __forceinline__ void mbar_expect_tx(uint32_t mb, uint32_t bytes) {
    asm volatile("mbarrier.arrive.expect_tx.shared.b64 _, [%0], %1;"
                 :: "r"(mb), "r"(bytes) : "memory");
}
__device__ __forceinline__ void bulk_g2s(uint32_t sdst, const void* gsrc,
                                         uint32_t bytes, uint32_t mb) {
    asm volatile(
        "cp.async.bulk.shared::cta.global.mbarrier::complete_tx::bytes "
        "[%0], [%1], %2, [%3];"
        :: "r"(sdst), "l"(gsrc), "r"(bytes), "r"(mb) : "memory");
}
__device__ __forceinline__ void mbar_wait(uint32_t mb, uint32_t parity) {
    uint32_t done;
    asm volatile(
        "{\n\t.reg .pred p;\n\t"
        "mbarrier.try_wait.parity.acquire.cta.shared::cta.b64 p, [%1], %2;\n\t"
        "selp.b32 %0, 1, 0, p;\n\t}"
        : "=r"(done) : "r"(mb), "r"(parity) : "memory");
    if (!done) {
        asm volatile(
            "{\n\t.reg .pred P1;\n\t"
            "WL_%=:\n\t"
            "mbarrier.try_wait.parity.acquire.cta.shared::cta.b64 P1, [%0], %1, 0x989680;\n\t"
            "@P1 bra.uni WD_%=;\n\t"
            "bra.uni WL_%=;\n\t"
            "WD_%=:\n\t}"
            :: "r"(mb), "r"(parity) : "memory");
    }
}

// ---- warp MMA primitives ---------------------------------------------------
__device__ __forceinline__ void ldmx4(uint32_t& r0, uint32_t& r1,
                                      uint32_t& r2, uint32_t& r3, uint32_t addr) {
    asm volatile("ldmatrix.sync.aligned.m8n8.x4.shared.b16 {%0,%1,%2,%3}, [%4];"
                 : "=r"(r0), "=r"(r1), "=r"(r2), "=r"(r3) : "r"(addr));
}

__device__ __forceinline__ void mma16816(float& d0, float& d1, float& d2, float& d3,
                                         uint32_t a0, uint32_t a1, uint32_t a2, uint32_t a3,
                                         uint32_t b0, uint32_t b1) {
    asm volatile(
        "mma.sync.aligned.m16n8k16.row.col.f32.bf16.bf16.f32 "
        "{%0,%1,%2,%3}, {%4,%5,%6,%7}, {%8,%9}, {%0,%1,%2,%3};"
        : "+f"(d0), "+f"(d1), "+f"(d2), "+f"(d3)
        : "r"(a0), "r"(a1), "r"(a2), "r"(a3), "r"(b0), "r"(b1));
}

// ---------------------------------------------------------------------------
// Prep: write one row as [hi(32 bf16) | lo(32 bf16)] = 128B, SW128-swizzled.
// ---------------------------------------------------------------------------
__device__ __forceinline__ void write_row_hilo(uint8_t* img, int r,
                                               const float* v) {
    uint32_t wd[32];
    #pragma unroll
    for (int k = 0; k < 16; k++) {
        float a = v[2 * k], b = v[2 * k + 1];
        wd[k] = pack_bf2(a, b);
        __nv_bfloat16 ha = __float2bfloat16(a), hb = __float2bfloat16(b);
        wd[16 + k] = pack_bf2(a - __bfloat162float(ha), b - __bfloat162float(hb));
    }
    uint8_t* base = img + (size_t)r * ROWB;
    uint32_t rb = ((uint32_t)r & 7) * 128;   // only bits [9:7] matter for swizzle
    #pragma unroll
    for (int g = 0; g < 8; g++) {
        uint32_t off = sw128(rb + g * 16) - rb;
        uint4 u = make_uint4(wd[4 * g], wd[4 * g + 1], wd[4 * g + 2], wd[4 * g + 3]);
        *reinterpret_cast<uint4*>(base + off) = u;
    }
}

__global__ void prep_x(const float* __restrict__ x, int N, int rpad) {
    int r = blockIdx.x * blockDim.x + threadIdx.x;
    if (r >= rpad) return;
    float v[D];
    if (r < N) {
        const float4* xp = reinterpret_cast<const float4*>(x + (size_t)r * D);
        #pragma unroll
        for (int q = 0; q < D / 4; q++) {
            float4 t = xp[q];
            v[4 * q] = t.x; v[4 * q + 1] = t.y; v[4 * q + 2] = t.z; v[4 * q + 3] = t.w;
        }
    } else {
        #pragma unroll
        for (int k = 0; k < D; k++) v[k] = 0.f;
    }
    float s = 0.f;
    #pragma unroll
    for (int k = 0; k < D; k++) s = fmaf(v[k], v[k], s);
    g_bx[r] = -0.5f * s * LOG2E;
    write_row_hilo(g_xI, r, v);
}

__global__ void prep_c(const float* __restrict__ c,
                       const float* __restrict__ beta, int M, int mpad) {
    int j = blockIdx.x * blockDim.x + threadIdx.x;
    if (j >= mpad) return;
    float v[D];
    float s = 0.f;
    if (j < M) {
        const float4* cp = reinterpret_cast<const float4*>(c + (size_t)j * D);
        #pragma unroll
        for (int q = 0; q < D / 4; q++) {
            float4 t = cp[q];
            v[4 * q] = t.x; v[4 * q + 1] = t.y; v[4 * q + 2] = t.z; v[4 * q + 3] = t.w;
        }
        #pragma unroll
        for (int k = 0; k < D; k++) {
            s = fmaf(v[k], v[k], s);
            v[k] *= LOG2E;                 // fold log2(e) into the B operand
        }
        float b = beta[j];
        g_G[j] = fmaf(-0.5f * LOG2E, s, log2f(b));
    } else {
        #pragma unroll
        for (int k = 0; k < D; k++) v[k] = 0.f;
        g_G[j] = -1e30f;                   // padded centers contribute exactly 0
    }
    write_row_hilo(g_cI, j, v);
}

// ---------------------------------------------------------------------------
// Main fused kernel: grid = N/64 CTAs, 128 threads (4 warps x m16 rows).
// smem: A 8KB | B0 16KB | B1 16KB | G0 512B | G1 512B | mbars
// ---------------------------------------------------------------------------
constexpr int SA   = 0;
constexpr int SB0  = 8192;
constexpr int SB1  = 24576;
constexpr int SG0  = 40960;
constexpr int SG1  = 41472;
constexpr int SMB  = 41984;               // mbA @+0, mbF0 @+8, mbF1 @+16
constexpr int STOT = 42048;

__global__ void __launch_bounds__(128)
krr_main(float* __restrict__ out, int N, int ntiles)
{
    __shared__ __align__(128) uint8_t smem[STOT];
    const uint32_t sbase = (uint32_t)__cvta_generic_to_shared(smem);

    const int tid  = threadIdx.x;
    const int w    = tid >> 5;
    const int lane = tid & 31;

    const uint32_t mbA = sbase + SMB;
    const uint32_t mbF[2] = {sbase + SMB + 8, sbase + SMB + 16};

    if (tid == 0) {
        mbar_init(mbA, 1);
        mbar_init(mbF[0], 1);
        mbar_init(mbF[1], 1);
    }
    asm volatile("fence.proxy.async.shared::cta;" ::: "memory");
    __syncthreads();

    if (tid == 0) {
        mbar_expect_tx(mbA, RC * ROWB);
        bulk_g2s(sbase + SA, g_xI + (size_t)blockIdx.x * RC * ROWB, RC * ROWB, mbA);
        mbar_expect_tx(mbF[0], NB * ROWB + NB * 4);
        bulk_g2s(sbase + SB0, g_cI, NB * ROWB, mbF[0]);
        bulk_g2s(sbase + SG0, g_G, NB * 4, mbF[0]);
        if (ntiles > 1) {
            mbar_expect_tx(mbF[1], NB * ROWB + NB * 4);
            bulk_g2s(sbase + SB1, g_cI + (size_t)NB * ROWB, NB * ROWB, mbF[1]);
            bulk_g2s(sbase + SG1, g_G + NB, NB * 4, mbF[1]);
        }
    }

    // ---- A fragments (once per kernel) ----
    mbar_wait(mbA, 0);
    const uint32_t l7   = lane & 7;
    const uint32_t arow = (uint32_t)w * 16 + (lane & 15);
    uint32_t a[16];
    #pragma unroll
    for (int kk = 0; kk < 4; kk++) {
        uint32_t chunk = 2 * kk + (lane >> 4);
        uint32_t addr  = sbase + SA + arow * 128 + ((chunk ^ l7) << 4);
        ldmx4(a[4 * kk], a[4 * kk + 1], a[4 * kk + 2], a[4 * kk + 3], addr);
    }

    // per-lane B address constants
    const uint32_t bsw0  = (((lane >> 3) ^ l7) << 4);  // k-chunks 0-3
    const uint32_t bsw1  = bsw0 ^ 0x40;                // k-chunks 4-7
    const uint32_t bloff = l7 * 128;

    float rs_lo = 0.f, rs_hi = 0.f;

    for (int t = 0; t < ntiles; t++) {
        const int buf = t & 1;
        mbar_wait(mbF[buf], (t >> 1) & 1);

        const uint32_t sB = sbase + (buf ? SB1 : SB0);
        const float2* G2 = reinterpret_cast<const float2*>(smem + (buf ? SG1 : SG0));

        #pragma unroll 4
        for (int g = 0; g < NB / 8; g++) {
            uint32_t b0, b1, b2, b3, b4, b5, b6, b7;
            uint32_t ba = sB + (uint32_t)g * 1024 + bloff;
            ldmx4(b0, b1, b2, b3, ba + bsw0);
            ldmx4(b4, b5, b6, b7, ba + bsw1);

            float d0 = 0.f, d1 = 0.f, d2 = 0.f, d3 = 0.f;
            mma16816(d0, d1, d2, d3, a[0],  a[1],  a[2],  a[3],  b0, b1);
            mma16816(d0, d1, d2, d3, a[4],  a[5],  a[6],  a[7],  b2, b3);
            mma16816(d0, d1, d2, d3, a[8],  a[9],  a[10], a[11], b4, b5);
            mma16816(d0, d1, d2, d3, a[12], a[13], a[14], a[15], b6, b7);

            float2 Gp = G2[g * 4 + (lane & 3)];
            rs_lo += ex2_approx(d0 + Gp.x) + ex2_approx(d1 + Gp.y);
            rs_hi += ex2_approx(d2 + Gp.x) + ex2_approx(d3 + Gp.y);
        }

        __syncthreads();
        if (tid == 0 && t + 2 < ntiles) {
            mbar_expect_tx(mbF[buf], NB * ROWB + NB * 4);
            bulk_g2s(sbase + (buf ? SB1 : SB0),
                     g_cI + (size_t)(t + 2) * NB * ROWB, NB * ROWB, mbF[buf]);
            bulk_g2s(sbase + (buf ? SG1 : SG0),
                     g_G + (size_t)(t + 2) * NB, NB * 4, mbF[buf]);
        }
    }

    // ---- per-row reduction across the 4 column-lanes, then writeback ----
    rs_lo += __shfl_xor_sync(0xffffffffu, rs_lo, 1);
    rs_lo += __shfl_xor_sync(0xffffffffu, rs_lo, 2);
    rs_hi += __shfl_xor_sync(0xffffffffu, rs_hi, 1);
    rs_hi += __shfl_xor_sync(0xffffffffu, rs_hi, 2);

    const int rbase = blockIdx.x * RC + w * 16 + (lane >> 2);
    if ((lane & 3) == 0) {
        int r = rbase;
        if (r < N) {
            float s = ex2_approx(g_bx[r]) * rs_lo;
            out[r] = s + log1pf(expf(-s));
        }
    } else if ((lane & 3) == 1) {
        int r = rbase + 8;
        if (r < N) {
            float s = ex2_approx(g_bx[r]) * rs_hi;
            out[r] = s + log1pf(expf(-s));
        }
    }
}

// ---------------------------------------------------------------------------
extern "C" void kernel_launch(void* const* d_in, const int* in_sizes, int n_in,
                              void* d_out, int out_size) {
    const float* x    = (const float*)d_in[0];  // (N, 32)
    const float* c    = (const float*)d_in[1];  // (M, 32)
    const float* beta = (const float*)d_in[2];  // (M,)
    float* out = (float*)d_out;                 // (N,)

    const int M = in_sizes[2];
    const int N = out_size;

    int nrt = (N + RC - 1) / RC;   if (nrt > MAXR / RC) nrt = MAXR / RC;
    int nct = (M + NB - 1) / NB;   if (nct > MAXM / NB) nct = MAXM / NB;
    const int rpad = nrt * RC;
    const int mpad = nct * NB;

    prep_x<<<(rpad + 255) / 256, 256>>>(x, N, rpad);
    prep_c<<<(mpad + 255) / 256, 256>>>(c, beta, M, mpad);
    krr_main<<<nrt, 128>>>(out, N, nct);
}

// round 6
// speedup vs baseline: 13.6239x; 1.5763x over previous
#include <cuda_runtime.h>
#include <cuda_bf16.h>
#include <cstdint>

// ---------------------------------------------------------------------------
// softplus( exp(-0.5*||x_i - c_j||^2) @ beta ),  N=40000, M=4000, D=32.
//
// R6: pure-bf16 K=32 GEMM on mma.sync.m16n8k16 + fused ex2 epilogue.
//   (R5's hi/lo split provably added nothing: it omitted the cross terms,
//    making it numerically == pure bf16, and still measured rel_err 7.8e-7.)
//   d   = bf16(x) . bf16(c * log2e)      (fp32 accum)
//   e   = ex2(d + G_j),  G_j = -0.5*||c||^2*log2e + log2(beta_j)
//   row = ex2(bx_i) * sum_j e
// x-rows are converted to the swizzled bf16 smem image INSIDE the main kernel
// (prep_x eliminated). Center image (64B/row, chunk-swizzled) + G built once
// by prep_c; tiles of 128 centers stream via cp.async.bulk + mbarrier.
// 96 rows/CTA, 6 warps (grid 417 -> wave imbalance 1.065).
// ---------------------------------------------------------------------------

#define LOG2E 1.4426950408889634f
typedef unsigned long long ull;

constexpr int D    = 32;
constexpr int RC   = 96;        // rows per CTA
constexpr int NB   = 128;       // centers per tile
constexpr int MAXM = 8192;      // padded center capacity
constexpr int ROWB = 64;        // bytes per bf16 image row (32 bf16)

__device__ __align__(128) uint8_t g_cI[(size_t)MAXM * ROWB];  // c*log2e, bf16, swizzled
__device__ float g_G[MAXM];     // -0.5*||c||^2*log2e + log2(beta);  -1e30 pad

__device__ __forceinline__ float ex2_approx(float x) {
    float r;
    asm("ex2.approx.ftz.f32 %0, %1;" : "=f"(r) : "f"(x));
    return r;
}

__device__ __forceinline__ uint32_t pack_bf2(float a, float b) {
    __nv_bfloat16 ha = __float2bfloat16(a), hb = __float2bfloat16(b);
    unsigned short ua = *reinterpret_cast<unsigned short*>(&ha);
    unsigned short ub = *reinterpret_cast<unsigned short*>(&hb);
    return (uint32_t)ua | ((uint32_t)ub << 16);
}

// ---- async copy / mbarrier -------------------------------------------------
__device__ __forceinline__ void mbar_init(uint32_t mb, int count) {
    asm volatile("mbarrier.init.shared.b64 [%0], %1;" :: "r"(mb), "r"(count) : "memory");
}
__device__ __forceinline__ void mbar_expect_tx(uint32_t mb, uint32_t bytes) {
    asm volatile("mbarrier.arrive.expect_tx.shared.b64 _, [%0], %1;"
                 :: "r"(mb), "r"(bytes) : "memory");
}
__device__ __forceinline__ void bulk_g2s(uint32_t sdst, const void* gsrc,
                                         uint32_t bytes, uint32_t mb) {
    asm volatile(
        "cp.async.bulk.shared::cta.global.mbarrier::complete_tx::bytes "
        "[%0], [%1], %2, [%3];"
        :: "r"(sdst), "l"(gsrc), "r"(bytes), "r"(mb) : "memory");
}
__device__ __forceinline__ void mbar_wait(uint32_t mb, uint32_t parity) {
    uint32_t done;
    asm volatile(
        "{\n\t.reg .pred p;\n\t"
        "mbarrier.try_wait.parity.acquire.cta.shared::cta.b64 p, [%1], %2;\n\t"
        "selp.b32 %0, 1, 0, p;\n\t}"
        : "=r"(done) : "r"(mb), "r"(parity) : "memory");
    if (!done) {
        asm volatile(
            "{\n\t.reg .pred P1;\n\t"
            "WL_%=:\n\t"
            "mbarrier.try_wait.parity.acquire.cta.shared::cta.b64 P1, [%0], %1, 0x989680;\n\t"
            "@P1 bra.uni WD_%=;\n\t"
            "bra.uni WL_%=;\n\t"
            "WD_%=:\n\t}"
            :: "r"(mb), "r"(parity) : "memory");
    }
}

// ---- warp MMA primitives ---------------------------------------------------
__device__ __forceinline__ void ldmx4(uint32_t& r0, uint32_t& r1,
                                      uint32_t& r2, uint32_t& r3, uint32_t addr) {
    asm volatile("ldmatrix.sync.aligned.m8n8.x4.shared.b16 {%0,%1,%2,%3}, [%4];"
                 : "=r"(r0), "=r"(r1), "=r"(r2), "=r"(r3) : "r"(addr));
}

__device__ __forceinline__ void mma16816(float& d0, float& d1, float& d2, float& d3,
                                         uint32_t a0, uint32_t a1, uint32_t a2, uint32_t a3,
                                         uint32_t b0, uint32_t b1) {
    asm volatile(
        "mma.sync.aligned.m16n8k16.row.col.f32.bf16.bf16.f32 "
        "{%0,%1,%2,%3}, {%4,%5,%6,%7}, {%8,%9}, {%0,%1,%2,%3};"
        : "+f"(d0), "+f"(d1), "+f"(d2), "+f"(d3)
        : "r"(a0), "r"(a1), "r"(a2), "r"(a3), "r"(b0), "r"(b1));
}

// ---------------------------------------------------------------------------
// prep_c: one thread per HALF center row (16 floats). Writes the 64B bf16
// image row with chunk swizzle  phys_chunk = logical_chunk ^ ((j>>1)&3),
// and G_j (half 0 only). Padded rows: zero image, G = -1e30.
// ---------------------------------------------------------------------------
__global__ void prep_c(const float* __restrict__ c,
                       const float* __restrict__ beta, int M, int mpad) {
    int idx  = blockIdx.x * blockDim.x + threadIdx.x;
    int j    = idx >> 1;
    int half = idx & 1;
    if (j >= mpad) return;

    float v[16];
    if (j < M) {
        const float4* cp = reinterpret_cast<const float4*>(c + (size_t)j * D + half * 16);
        #pragma unroll
        for (int q = 0; q < 4; q++) {
            float4 t = cp[q];
            v[4 * q] = t.x; v[4 * q + 1] = t.y; v[4 * q + 2] = t.z; v[4 * q + 3] = t.w;
        }
    } else {
        #pragma unroll
        for (int k = 0; k < 16; k++) v[k] = 0.f;
    }
    float s = 0.f;
    #pragma unroll
    for (int k = 0; k < 16; k++) {
        s = fmaf(v[k], v[k], s);
        v[k] *= LOG2E;
    }
    s += __shfl_xor_sync(0xffffffffu, s, 1);   // full ||c||^2 (pair shares warp)

    uint32_t wd[8];
    #pragma unroll
    for (int k = 0; k < 8; k++) wd[k] = pack_bf2(v[2 * k], v[2 * k + 1]);

    const uint32_t key = ((uint32_t)j >> 1) & 3;
    uint8_t* base = g_cI + (size_t)j * ROWB;
    #pragma unroll
    for (int cch = 0; cch < 2; cch++) {
        uint32_t lch = (uint32_t)half * 2 + cch;
        uint4 u = make_uint4(wd[4 * cch], wd[4 * cch + 1], wd[4 * cch + 2], wd[4 * cch + 3]);
        *reinterpret_cast<uint4*>(base + ((lch ^ key) << 4)) = u;
    }

    if (half == 0)
        g_G[j] = (j < M) ? fmaf(-0.5f * LOG2E, s, log2f(beta[j])) : -1e30f;
}

// ---------------------------------------------------------------------------
// Main fused kernel: grid = ceil(N/96), 192 threads (6 warps x m16 rows).
// smem: A 6KB | B0 8KB | B1 8KB | G0 512B | G1 512B | bx 384B | mbars
// ---------------------------------------------------------------------------
constexpr int SA   = 0;
constexpr int SB0  = 6144;
constexpr int SB1  = 14336;
constexpr int SG0  = 22528;
constexpr int SG1  = 23040;
constexpr int SBX  = 23552;
constexpr int SMB  = 23936;      // mbF0 @+0, mbF1 @+8
constexpr int STOT = 23952;

__global__ void __launch_bounds__(192)
krr_main(const float* __restrict__ x, float* __restrict__ out, int N, int ntiles)
{
    __shared__ __align__(128) uint8_t smem[STOT];
    const uint32_t sbase = (uint32_t)__cvta_generic_to_shared(smem);

    const int tid  = threadIdx.x;
    const int w    = tid >> 5;
    const int lane = tid & 31;

    const uint32_t mbF[2] = {sbase + SMB, sbase + SMB + 8};

    if (tid == 0) {
        mbar_init(mbF[0], 1);
        mbar_init(mbF[1], 1);
    }
    asm volatile("fence.proxy.async.shared::cta;" ::: "memory");
    __syncthreads();

    if (tid == 0) {
        mbar_expect_tx(mbF[0], NB * ROWB + NB * 4);
        bulk_g2s(sbase + SB0, g_cI, NB * ROWB, mbF[0]);
        bulk_g2s(sbase + SG0, g_G, NB * 4, mbF[0]);
        if (ntiles > 1) {
            mbar_expect_tx(mbF[1], NB * ROWB + NB * 4);
            bulk_g2s(sbase + SB1, g_cI + (size_t)NB * ROWB, NB * ROWB, mbF[1]);
            bulk_g2s(sbase + SG1, g_G + NB, NB * 4, mbF[1]);
        }
    }

    // ---- convert this CTA's 96 x-rows into the swizzled bf16 A image ------
    // thread -> half row: row r = tid>>1, half = tid&1 (coalesced 64B/thread)
    {
        int r    = tid >> 1;
        int half = tid & 1;
        int gr   = blockIdx.x * RC + r;
        if (gr > N - 1) gr = N - 1;

        float v[16];
        const float4* xp = reinterpret_cast<const float4*>(x + (size_t)gr * D + half * 16);
        #pragma unroll
        for (int q = 0; q < 4; q++) {
            float4 t = xp[q];
            v[4 * q] = t.x; v[4 * q + 1] = t.y; v[4 * q + 2] = t.z; v[4 * q + 3] = t.w;
        }
        float s = 0.f;
        #pragma unroll
        for (int k = 0; k < 16; k++) s = fmaf(v[k], v[k], s);
        s += __shfl_xor_sync(0xffffffffu, s, 1);

        uint32_t wd[8];
        #pragma unroll
        for (int k = 0; k < 8; k++) wd[k] = pack_bf2(v[2 * k], v[2 * k + 1]);

        const uint32_t key = ((uint32_t)r >> 1) & 3;
        uint8_t* abase = smem + SA + r * ROWB;
        #pragma unroll
        for (int cch = 0; cch < 2; cch++) {
            uint32_t lch = (uint32_t)half * 2 + cch;
            uint4 u = make_uint4(wd[4 * cch], wd[4 * cch + 1], wd[4 * cch + 2], wd[4 * cch + 3]);
            *reinterpret_cast<uint4*>(abase + ((lch ^ key) << 4)) = u;
        }
        if (half == 0)
            *reinterpret_cast<float*>(smem + SBX + r * 4) = -0.5f * s * LOG2E;
    }
    __syncthreads();

    // ---- A fragments (once) ----
    const uint32_t arow = (uint32_t)w * 16 + (lane & 15);
    const uint32_t akey = (arow >> 1) & 3;
    uint32_t a[8];
    {
        uint32_t ad0 = sbase + SA + arow * ROWB + ((((uint32_t)(lane >> 4) + 0) ^ akey) << 4);
        uint32_t ad1 = sbase + SA + arow * ROWB + ((((uint32_t)(lane >> 4) + 2) ^ akey) << 4);
        ldmx4(a[0], a[1], a[2], a[3], ad0);   // k 0-15
        ldmx4(a[4], a[5], a[6], a[7], ad1);   // k 16-31
    }

    // per-lane B address constant: row = lane&7, chunk = lane>>3 (swizzled)
    const uint32_t l7 = lane & 7;
    const uint32_t boff = l7 * ROWB + ((((uint32_t)lane >> 3) ^ ((l7 >> 1) & 3)) << 4);

    float rs_lo = 0.f, rs_hi = 0.f;

    for (int t = 0; t < ntiles; t++) {
        const int buf = t & 1;
        mbar_wait(mbF[buf], (t >> 1) & 1);

        const uint32_t sB = sbase + (buf ? SB1 : SB0);
        const float2* G2 = reinterpret_cast<const float2*>(smem + (buf ? SG1 : SG0));

        #pragma unroll 4
        for (int g = 0; g < NB / 8; g++) {
            uint32_t b0, b1, b2, b3;
            ldmx4(b0, b1, b2, b3, sB + (uint32_t)g * (8 * ROWB) + boff);

            float d0 = 0.f, d1 = 0.f, d2 = 0.f, d3 = 0.f;
            mma16816(d0, d1, d2, d3, a[0], a[1], a[2], a[3], b0, b1);
            mma16816(d0, d1, d2, d3, a[4], a[5], a[6], a[7], b2, b3);

            float2 Gp = G2[g * 4 + (lane & 3)];
            rs_lo += ex2_approx(d0 + Gp.x) + ex2_approx(d1 + Gp.y);
            rs_hi += ex2_approx(d2 + Gp.x) + ex2_approx(d3 + Gp.y);
        }

        __syncthreads();
        if (tid == 0 && t + 2 < ntiles) {
            mbar_expect_tx(mbF[buf], NB * ROWB + NB * 4);
            bulk_g2s(sbase + (buf ? SB1 : SB0),
                     g_cI + (size_t)(t + 2) * NB * ROWB, NB * ROWB, mbF[buf]);
            bulk_g2s(sbase + (buf ? SG1 : SG0),
                     g_G + (size_t)(t + 2) * NB, NB * 4, mbF[buf]);
        }
    }

    // ---- reduce across the 4 column-lanes and write ----
    rs_lo += __shfl_xor_sync(0xffffffffu, rs_lo, 1);
    rs_lo += __shfl_xor_sync(0xffffffffu, rs_lo, 2);
    rs_hi += __shfl_xor_sync(0xffffffffu, rs_hi, 1);
    rs_hi += __shfl_xor_sync(0xffffffffu, rs_hi, 2);

    const int lrow = w * 16 + (lane >> 2);
    const float* bxp = reinterpret_cast<const float*>(smem + SBX);
    if ((lane & 3) == 0) {
        int r = blockIdx.x * RC + lrow;
        if (r < N) {
            float s = ex2_approx(bxp[lrow]) * rs_lo;
            out[r] = s + log1pf(expf(-s));
        }
    } else if ((lane & 3) == 1) {
        int r = blockIdx.x * RC + lrow + 8;
        if (r < N) {
            float s = ex2_approx(bxp[lrow + 8]) * rs_hi;
            out[r] = s + log1pf(expf(-s));
        }
    }
}

// ---------------------------------------------------------------------------
extern "C" void kernel_launch(void* const* d_in, const int* in_sizes, int n_in,
                              void* d_out, int out_size) {
    const float* x    = (const float*)d_in[0];  // (N, 32)
    const float* c    = (const float*)d_in[1];  // (M, 32)
    const float* beta = (const float*)d_in[2];  // (M,)
    float* out = (float*)d_out;                 // (N,)

    const int M = in_sizes[2];
    const int N = out_size;

    int nct = (M + NB - 1) / NB;
    if (nct > MAXM / NB) nct = MAXM / NB;
    const int mpad = nct * NB;

    prep_c<<<(mpad * 2 + 255) / 256, 256>>>(c, beta, M, mpad);

    const int grid = (N + RC - 1) / RC;
    krr_main<<<grid, 192>>>(x, out, N, nct);
}

// round 7
// speedup vs baseline: 15.5396x; 1.1406x over previous
#include <cuda_runtime.h>
#include <cuda_bf16.h>
#include <cstdint>

// ---------------------------------------------------------------------------
// softplus( exp(-0.5*||x_i - c_j||^2) @ beta ),  N=40000, M=4000, D=32.
//
// R7: bf16 K=32 mma.sync GEMM, fused ex2 epilogue, with
//   (a) G folded into the MMA accumulator seed (C-operand does d+G for free)
//   (b) warp-pair center-split: 384 thr/CTA, each 16-row group processed by
//       2 warps on opposite halves of the 128-center tile -> 36 warps/SM,
//       covering MUFU/LDS latency. Partials combined through smem.
//   d   = bf16(x) . bf16(c*log2e) + G_j   (fp32 accum, seeded)
//   e   = ex2(d);  row = ex2(bx_i) * sum_j e;  out = softplus(row)
// ---------------------------------------------------------------------------

#define LOG2E 1.4426950408889634f
typedef unsigned long long ull;

constexpr int D    = 32;
constexpr int RC   = 96;        // rows per CTA
constexpr int NB   = 128;       // centers per tile
constexpr int MAXM = 8192;      // padded center capacity
constexpr int ROWB = 64;        // bytes per bf16 image row (32 bf16)

__device__ __align__(128) uint8_t g_cI[(size_t)MAXM * ROWB];  // c*log2e, bf16, swizzled
__device__ float g_G[MAXM];     // -0.5*||c||^2*log2e + log2(beta);  -1e30 pad

__device__ __forceinline__ float ex2_approx(float x) {
    float r;
    asm("ex2.approx.ftz.f32 %0, %1;" : "=f"(r) : "f"(x));
    return r;
}

__device__ __forceinline__ uint32_t pack_bf2(float a, float b) {
    __nv_bfloat16 ha = __float2bfloat16(a), hb = __float2bfloat16(b);
    unsigned short ua = *reinterpret_cast<unsigned short*>(&ha);
    unsigned short ub = *reinterpret_cast<unsigned short*>(&hb);
    return (uint32_t)ua | ((uint32_t)ub << 16);
}

// ---- async copy / mbarrier -------------------------------------------------
__device__ __forceinline__ void mbar_init(uint32_t mb, int count) {
    asm volatile("mbarrier.init.shared.b64 [%0], %1;" :: "r"(mb), "r"(count) : "memory");
}
__device__ __forceinline__ void mbar_expect_tx(uint32_t mb, uint32_t bytes) {
    asm volatile("mbarrier.arrive.expect_tx.shared.b64 _, [%0], %1;"
                 :: "r"(mb), "r"(bytes) : "memory");
}
__device__ __forceinline__ void bulk_g2s(uint32_t sdst, const void* gsrc,
                                         uint32_t bytes, uint32_t mb) {
    asm volatile(
        "cp.async.bulk.shared::cta.global.mbarrier::complete_tx::bytes "
        "[%0], [%1], %2, [%3];"
        :: "r"(sdst), "l"(gsrc), "r"(bytes), "r"(mb) : "memory");
}
__device__ __forceinline__ void mbar_wait(uint32_t mb, uint32_t parity) {
    uint32_t done;
    asm volatile(
        "{\n\t.reg .pred p;\n\t"
        "mbarrier.try_wait.parity.acquire.cta.shared::cta.b64 p, [%1], %2;\n\t"
        "selp.b32 %0, 1, 0, p;\n\t}"
        : "=r"(done) : "r"(mb), "r"(parity) : "memory");
    if (!done) {
        asm volatile(
            "{\n\t.reg .pred P1;\n\t"
            "WL_%=:\n\t"
            "mbarrier.try_wait.parity.acquire.cta.shared::cta.b64 P1, [%0], %1, 0x989680;\n\t"
            "@P1 bra.uni WD_%=;\n\t"
            "bra.uni WL_%=;\n\t"
            "WD_%=:\n\t}"
            :: "r"(mb), "r"(parity) : "memory");
    }
}

// ---- warp MMA primitives ---------------------------------------------------
__device__ __forceinline__ void ldmx4(uint32_t& r0, uint32_t& r1,
                                      uint32_t& r2, uint32_t& r3, uint32_t addr) {
    asm volatile("ldmatrix.sync.aligned.m8n8.x4.shared.b16 {%0,%1,%2,%3}, [%4];"
                 : "=r"(r0), "=r"(r1), "=r"(r2), "=r"(r3) : "r"(addr));
}

__device__ __forceinline__ void mma16816(float& d0, float& d1, float& d2, float& d3,
                                         uint32_t a0, uint32_t a1, uint32_t a2, uint32_t a3,
                                         uint32_t b0, uint32_t b1) {
    asm volatile(
        "mma.sync.aligned.m16n8k16.row.col.f32.bf16.bf16.f32 "
        "{%0,%1,%2,%3}, {%4,%5,%6,%7}, {%8,%9}, {%0,%1,%2,%3};"
        : "+f"(d0), "+f"(d1), "+f"(d2), "+f"(d3)
        : "r"(a0), "r"(a1), "r"(a2), "r"(a3), "r"(b0), "r"(b1));
}

// ---------------------------------------------------------------------------
// prep_c: one thread per HALF center row (16 floats). Writes the 64B bf16
// image row with chunk swizzle  phys_chunk = logical_chunk ^ ((j>>1)&3),
// and G_j (half 0 only). Padded rows: zero image, G = -1e30.
// ---------------------------------------------------------------------------
__global__ void prep_c(const float* __restrict__ c,
                       const float* __restrict__ beta, int M, int mpad) {
    int idx  = blockIdx.x * blockDim.x + threadIdx.x;
    int j    = idx >> 1;
    int half = idx & 1;
    if (j >= mpad) return;

    float v[16];
    if (j < M) {
        const float4* cp = reinterpret_cast<const float4*>(c + (size_t)j * D + half * 16);
        #pragma unroll
        for (int q = 0; q < 4; q++) {
            float4 t = cp[q];
            v[4 * q] = t.x; v[4 * q + 1] = t.y; v[4 * q + 2] = t.z; v[4 * q + 3] = t.w;
        }
    } else {
        #pragma unroll
        for (int k = 0; k < 16; k++) v[k] = 0.f;
    }
    float s = 0.f;
    #pragma unroll
    for (int k = 0; k < 16; k++) {
        s = fmaf(v[k], v[k], s);
        v[k] *= LOG2E;
    }
    s += __shfl_xor_sync(0xffffffffu, s, 1);   // full ||c||^2 (pair in same warp)

    uint32_t wd[8];
    #pragma unroll
    for (int k = 0; k < 8; k++) wd[k] = pack_bf2(v[2 * k], v[2 * k + 1]);

    const uint32_t key = ((uint32_t)j >> 1) & 3;
    uint8_t* base = g_cI + (size_t)j * ROWB;
    #pragma unroll
    for (int cch = 0; cch < 2; cch++) {
        uint32_t lch = (uint32_t)half * 2 + cch;
        uint4 u = make_uint4(wd[4 * cch], wd[4 * cch + 1], wd[4 * cch + 2], wd[4 * cch + 3]);
        *reinterpret_cast<uint4*>(base + ((lch ^ key) << 4)) = u;
    }

    if (half == 0)
        g_G[j] = (j < M) ? fmaf(-0.5f * LOG2E, s, log2f(beta[j])) : -1e30f;
}

// ---------------------------------------------------------------------------
// Main fused kernel: grid = ceil(N/96), 384 threads (12 warps).
// Warp pair (wp = w>>1) owns rows [wp*16, wp*16+16); half = w&1 selects which
// 64 centers of the 128-tile the warp processes. smem layout:
//   A 6KB | B0 8KB | B1 8KB | G0 512B | G1 512B | bx 384B | red 768B | mbars
// ---------------------------------------------------------------------------
constexpr int SA   = 0;
constexpr int SB0  = 6144;
constexpr int SB1  = 14336;
constexpr int SG0  = 22528;
constexpr int SG1  = 23040;
constexpr int SBX  = 23552;
constexpr int SRED = 23936;          // float[2][96]
constexpr int SMB  = 24704;          // mbF0 @+0, mbF1 @+8
constexpr int STOT = 24720;

__global__ void __launch_bounds__(384)
krr_main(const float* __restrict__ x, float* __restrict__ out, int N, int ntiles)
{
    __shared__ __align__(128) uint8_t smem[STOT];
    const uint32_t sbase = (uint32_t)__cvta_generic_to_shared(smem);

    const int tid  = threadIdx.x;
    const int w    = tid >> 5;
    const int lane = tid & 31;
    const int wp   = w >> 1;       // row group 0..5
    const int half = w & 1;        // center half 0/1

    const uint32_t mbF[2] = {sbase + SMB, sbase + SMB + 8};

    if (tid == 0) {
        mbar_init(mbF[0], 1);
        mbar_init(mbF[1], 1);
    }
    asm volatile("fence.proxy.async.shared::cta;" ::: "memory");
    __syncthreads();

    if (tid == 0) {
        mbar_expect_tx(mbF[0], NB * ROWB + NB * 4);
        bulk_g2s(sbase + SB0, g_cI, NB * ROWB, mbF[0]);
        bulk_g2s(sbase + SG0, g_G, NB * 4, mbF[0]);
        if (ntiles > 1) {
            mbar_expect_tx(mbF[1], NB * ROWB + NB * 4);
            bulk_g2s(sbase + SB1, g_cI + (size_t)NB * ROWB, NB * ROWB, mbF[1]);
            bulk_g2s(sbase + SG1, g_G + NB, NB * 4, mbF[1]);
        }
    }

    // ---- convert this CTA's 96 x-rows into the swizzled bf16 A image ------
    if (tid < 192) {
        int r    = tid >> 1;
        int hh   = tid & 1;
        int gr   = blockIdx.x * RC + r;
        if (gr > N - 1) gr = N - 1;

        float v[16];
        const float4* xp = reinterpret_cast<const float4*>(x + (size_t)gr * D + hh * 16);
        #pragma unroll
        for (int q = 0; q < 4; q++) {
            float4 t = xp[q];
            v[4 * q] = t.x; v[4 * q + 1] = t.y; v[4 * q + 2] = t.z; v[4 * q + 3] = t.w;
        }
        float s = 0.f;
        #pragma unroll
        for (int k = 0; k < 16; k++) s = fmaf(v[k], v[k], s);
        s += __shfl_xor_sync(0xffffffffu, s, 1);

        uint32_t wd[8];
        #pragma unroll
        for (int k = 0; k < 8; k++) wd[k] = pack_bf2(v[2 * k], v[2 * k + 1]);

        const uint32_t key = ((uint32_t)r >> 1) & 3;
        uint8_t* abase = smem + SA + r * ROWB;
        #pragma unroll
        for (int cch = 0; cch < 2; cch++) {
            uint32_t lch = (uint32_t)hh * 2 + cch;
            uint4 u = make_uint4(wd[4 * cch], wd[4 * cch + 1], wd[4 * cch + 2], wd[4 * cch + 3]);
            *reinterpret_cast<uint4*>(abase + ((lch ^ key) << 4)) = u;
        }
        if (hh == 0)
            *reinterpret_cast<float*>(smem + SBX + r * 4) = -0.5f * s * LOG2E;
    }
    __syncthreads();

    // ---- A fragments (once per warp) ----
    const uint32_t arow = (uint32_t)wp * 16 + (lane & 15);
    const uint32_t akey = (arow >> 1) & 3;
    uint32_t a[8];
    {
        uint32_t ad0 = sbase + SA + arow * ROWB + ((((uint32_t)(lane >> 4) + 0) ^ akey) << 4);
        uint32_t ad1 = sbase + SA + arow * ROWB + ((((uint32_t)(lane >> 4) + 2) ^ akey) << 4);
        ldmx4(a[0], a[1], a[2], a[3], ad0);   // k 0-15
        ldmx4(a[4], a[5], a[6], a[7], ad1);   // k 16-31
    }

    // per-lane B address constant: row = lane&7, chunk = lane>>3 (swizzled)
    const uint32_t l7 = lane & 7;
    const uint32_t boff = l7 * ROWB + ((((uint32_t)lane >> 3) ^ ((l7 >> 1) & 3)) << 4);
    const uint32_t gbase = (uint32_t)half * 8;   // this warp's first group

    float rs_lo = 0.f, rs_hi = 0.f;

    for (int t = 0; t < ntiles; t++) {
        const int buf = t & 1;
        mbar_wait(mbF[buf], (t >> 1) & 1);

        const uint32_t sB = sbase + (buf ? SB1 : SB0);
        const float2* G2 = reinterpret_cast<const float2*>(smem + (buf ? SG1 : SG0));

        #pragma unroll 4
        for (int gg = 0; gg < 8; gg++) {
            const uint32_t g = gbase + gg;
            uint32_t b0, b1, b2, b3;
            ldmx4(b0, b1, b2, b3, sB + g * (8 * ROWB) + boff);

            // seed accumulators with G (the mma C-operand add does d+G)
            float2 Gp = G2[g * 4 + (lane & 3)];
            float d0 = Gp.x, d1 = Gp.y, d2 = Gp.x, d3 = Gp.y;
            mma16816(d0, d1, d2, d3, a[0], a[1], a[2], a[3], b0, b1);
            mma16816(d0, d1, d2, d3, a[4], a[5], a[6], a[7], b2, b3);

            rs_lo += ex2_approx(d0) + ex2_approx(d1);
            rs_hi += ex2_approx(d2) + ex2_approx(d3);
        }

        __syncthreads();
        if (tid == 0 && t + 2 < ntiles) {
            mbar_expect_tx(mbF[buf], NB * ROWB + NB * 4);
            bulk_g2s(sbase + (buf ? SB1 : SB0),
                     g_cI + (size_t)(t + 2) * NB * ROWB, NB * ROWB, mbF[buf]);
            bulk_g2s(sbase + (buf ? SG1 : SG0),
                     g_G + (size_t)(t + 2) * NB, NB * 4, mbF[buf]);
        }
    }

    // ---- reduce across the 4 column-lanes, deposit per-half partials ----
    rs_lo += __shfl_xor_sync(0xffffffffu, rs_lo, 1);
    rs_lo += __shfl_xor_sync(0xffffffffu, rs_lo, 2);
    rs_hi += __shfl_xor_sync(0xffffffffu, rs_hi, 1);
    rs_hi += __shfl_xor_sync(0xffffffffu, rs_hi, 2);

    float* red = reinterpret_cast<float*>(smem + SRED);
    const int lrow = wp * 16 + (lane >> 2);
    if ((lane & 3) == 0) red[half * 96 + lrow]     = rs_lo;
    if ((lane & 3) == 1) red[half * 96 + lrow + 8] = rs_hi;
    __syncthreads();

    // ---- combine halves, apply row factor + softplus, write ----
    if (tid < RC) {
        int r = blockIdx.x * RC + tid;
        if (r < N) {
            const float* bxp = reinterpret_cast<const float*>(smem + SBX);
            float s = ex2_approx(bxp[tid]) * (red[tid] + red[96 + tid]);
            out[r] = s + log1pf(expf(-s));
        }
    }
}

// ---------------------------------------------------------------------------
extern "C" void kernel_launch(void* const* d_in, const int* in_sizes, int n_in,
                              void* d_out, int out_size) {
    const float* x    = (const float*)d_in[0];  // (N, 32)
    const float* c    = (const float*)d_in[1];  // (M, 32)
    const float* beta = (const float*)d_in[2];  // (M,)
    float* out = (float*)d_out;                 // (N,)

    const int M = in_sizes[2];
    const int N = out_size;

    int nct = (M + NB - 1) / NB;
    if (nct > MAXM / NB) nct = MAXM / NB;
    const int mpad = nct * NB;

    prep_c<<<(mpad * 2 + 255) / 256, 256>>>(c, beta, M, mpad);

    const int grid = (N + RC - 1) / RC;
    krr_main<<<grid, 384>>>(x, out, N, nct);
}